// round 1
// baseline (speedup 1.0000x reference)
#include <cuda_runtime.h>
#include <math.h>

#define BB   16
#define LQ   2048
#define LK   2048
#define DD   64
#define DV   64
#define FLOAT_MIN_F (-3.4028234663852886e38f)

// Scratch (device globals are the sanctioned scratch mechanism).
__device__ float g_S[(long long)BB * LQ * LK];   // 268 MB raw scores
__device__ float g_m[BB * LK];                   // per-(b,k) column max
__device__ float g_rz[BB * LK];                  // per-(b,k) 1/Z

// ---------------------------------------------------------------------------
// Phase 1: S = QK^T/8 + max(log(mask),FLT_MIN); write S; column max & sum(exp)
// Block: 128 k-columns of one batch. 256 threads, 8x8 micro-tiles over
// a 128(q) x 128(k) score tile. Columns assigned strided (tx + 16*j) so the
// mask loads / S stores are coalesced.
// ---------------------------------------------------------------------------
__global__ __launch_bounds__(256) void p1_kernel(const float* __restrict__ Q,
                                                 const float* __restrict__ K,
                                                 const float* __restrict__ mask) {
    extern __shared__ float sm[];
    float* Ks    = sm;                 // [64][128] transposed: Ks[d*128+k]
    float* Qs    = Ks + 64 * 128;      // [64][128] transposed
    float* red   = Qs + 64 * 128;      // [16][128]
    float* m_run = red + 16 * 128;     // [128]
    float* z_run = m_run + 128;        // [128]

    const int b  = blockIdx.y;
    const int k0 = blockIdx.x * 128;
    const int tid = threadIdx.x;
    const int ty = tid >> 4;           // 0..15 (row group)
    const int tx = tid & 15;           // 0..15 (col group, strided cols)

    // Load K tile transposed (once per block)
    for (int i = tid; i < 128 * DD; i += 256) {
        int k = i >> 6, d = i & 63;
        Ks[d * 128 + k] = K[((long long)b * LK + k0 + k) * DD + d];
    }
    if (tid < 128) { m_run[tid] = -INFINITY; z_run[tid] = 0.0f; }
    __syncthreads();

    for (int q0 = 0; q0 < LQ; q0 += 128) {
        // Load Q tile transposed
        for (int i = tid; i < 128 * DD; i += 256) {
            int q = i >> 6, d = i & 63;
            Qs[d * 128 + q] = Q[((long long)b * LQ + q0 + q) * DD + d];
        }
        __syncthreads();

        float acc[8][8];
#pragma unroll
        for (int i = 0; i < 8; i++)
#pragma unroll
            for (int j = 0; j < 8; j++) acc[i][j] = 0.0f;

#pragma unroll 8
        for (int d = 0; d < DD; d++) {
            float a[8], bv[8];
#pragma unroll
            for (int i = 0; i < 8; i++) a[i] = Qs[d * 128 + ty * 8 + i];
#pragma unroll
            for (int j = 0; j < 8; j++) bv[j] = Ks[d * 128 + tx + 16 * j];
#pragma unroll
            for (int i = 0; i < 8; i++)
#pragma unroll
                for (int j = 0; j < 8; j++) acc[i][j] = fmaf(a[i], bv[j], acc[i][j]);
        }

        // Epilogue: scale, mask bias, write S, local per-column max
        float lmax[8];
#pragma unroll
        for (int j = 0; j < 8; j++) lmax[j] = -INFINITY;
#pragma unroll
        for (int i = 0; i < 8; i++) {
            const int q = q0 + ty * 8 + i;
#pragma unroll
            for (int j = 0; j < 8; j++) {
                const int k = k0 + tx + 16 * j;
                float s = acc[i][j] * 0.125f +
                          fmaxf(__logf(mask[(long long)q * LK + k]), FLOAT_MIN_F);
                acc[i][j] = s;
                g_S[((long long)b * LQ + q) * LK + k] = s;
                lmax[j] = fmaxf(lmax[j], s);
            }
        }
#pragma unroll
        for (int j = 0; j < 8; j++) red[ty * 128 + tx + 16 * j] = lmax[j];
        __syncthreads();

        // Update running max (+ rescale running sum)
        if (tid < 128) {
            float tm = red[tid];
#pragma unroll
            for (int r = 1; r < 16; r++) tm = fmaxf(tm, red[r * 128 + tid]);
            float m_new = fmaxf(m_run[tid], tm);
            z_run[tid] *= __expf(m_run[tid] - m_new);   // 0*0 on first tile: ok
            m_run[tid] = m_new;
        }
        __syncthreads();

        // Sum exp(s - m_new) over this tile
        float lsum[8];
#pragma unroll
        for (int j = 0; j < 8; j++) {
            const float mn = m_run[tx + 16 * j];
            float s = 0.0f;
#pragma unroll
            for (int i = 0; i < 8; i++) s += __expf(acc[i][j] - mn);
            lsum[j] = s;
        }
#pragma unroll
        for (int j = 0; j < 8; j++) red[ty * 128 + tx + 16 * j] = lsum[j];
        __syncthreads();
        if (tid < 128) {
            float ts = 0.0f;
#pragma unroll
            for (int r = 0; r < 16; r++) ts += red[r * 128 + tid];
            z_run[tid] += ts;
        }
        __syncthreads();
    }

    if (tid < 128) {
        g_m[b * LK + k0 + tid]  = m_run[tid];
        g_rz[b * LK + k0 + tid] = 1.0f / z_run[tid];    // z >= 1 always
    }
}

// ---------------------------------------------------------------------------
// Phase 2: out[b,q,:] = sum_k exp(S - m[k]) * rz[k] * V[k,:]
// Block: 128 q-rows x 64 v-cols of one batch. 128 threads, 8x8 micro-tiles.
// k processed in 64-wide tiles: P tile generated into smem, then P@V.
// ---------------------------------------------------------------------------
__global__ __launch_bounds__(128) void p2_kernel(const float* __restrict__ V,
                                                 float* __restrict__ out) {
    extern __shared__ float sm[];
    float* Ps  = sm;                   // [128][64]
    float* Vs  = Ps + 128 * 64;        // [64][64]
    float* ms  = Vs + 64 * 64;         // [64]
    float* rzs = ms + 64;              // [64]

    const int b  = blockIdx.y;
    const int q0 = blockIdx.x * 128;
    const int tid = threadIdx.x;
    const int ty = tid >> 3;           // 0..15
    const int tx = tid & 7;            // 0..7

    float acc[8][8];
#pragma unroll
    for (int i = 0; i < 8; i++)
#pragma unroll
        for (int j = 0; j < 8; j++) acc[i][j] = 0.0f;

    for (int kk0 = 0; kk0 < LK; kk0 += 64) {
        __syncthreads();   // previous tile fully consumed
        if (tid < 64) {
            ms[tid]  = g_m[b * LK + kk0 + tid];
            rzs[tid] = g_rz[b * LK + kk0 + tid];
        }
        // Load V tile [64 k][64 v]
        for (int i = tid; i < 64 * 64; i += 128) {
            int k = i >> 6, v = i & 63;
            Vs[k * 64 + v] = V[((long long)b * LK + kk0 + k) * DV + v];
        }
        __syncthreads();

        // Generate P tile [128 q][64 k] = exp(S - m) * rz (coalesced S reads)
        for (int i = tid; i < 128 * 64; i += 128) {
            int q = i >> 6, kk = i & 63;
            float s = g_S[((long long)b * LQ + q0 + q) * LK + kk0 + kk];
            Ps[q * 64 + kk] = __expf(s - ms[kk]) * rzs[kk];
        }
        __syncthreads();

        // acc += P @ V over 64 k
#pragma unroll 8
        for (int k = 0; k < 64; k++) {
            float a[8], bv[8];
#pragma unroll
            for (int i = 0; i < 8; i++) a[i] = Ps[(ty * 8 + i) * 64 + k];
#pragma unroll
            for (int j = 0; j < 8; j++) bv[j] = Vs[k * 64 + tx * 8 + j];
#pragma unroll
            for (int i = 0; i < 8; i++)
#pragma unroll
                for (int j = 0; j < 8; j++) acc[i][j] = fmaf(a[i], bv[j], acc[i][j]);
        }
    }

    // Write output
#pragma unroll
    for (int i = 0; i < 8; i++) {
        const int q = q0 + ty * 8 + i;
        float* orow = &out[((long long)b * LQ + q) * DV + tx * 8];
        float4 v0 = make_float4(acc[i][0], acc[i][1], acc[i][2], acc[i][3]);
        float4 v1 = make_float4(acc[i][4], acc[i][5], acc[i][6], acc[i][7]);
        reinterpret_cast<float4*>(orow)[0] = v0;
        reinterpret_cast<float4*>(orow)[1] = v1;
    }
}

// ---------------------------------------------------------------------------

extern "C" void kernel_launch(void* const* d_in, const int* in_sizes, int n_in,
                              void* d_out, int out_size) {
    const float* Q    = (const float*)d_in[0];
    const float* K    = (const float*)d_in[1];
    const float* V    = (const float*)d_in[2];
    const float* mask = (const float*)d_in[3];
    float* out        = (float*)d_out;

    const int P1_SMEM = (64 * 128 * 2 + 16 * 128 + 256) * (int)sizeof(float); // 74752 B
    const int P2_SMEM = (128 * 64 + 64 * 64 + 128) * (int)sizeof(float);      // 49664 B

    cudaFuncSetAttribute(p1_kernel, cudaFuncAttributeMaxDynamicSharedMemorySize, P1_SMEM);
    cudaFuncSetAttribute(p2_kernel, cudaFuncAttributeMaxDynamicSharedMemorySize, P2_SMEM);

    dim3 g1(LK / 128, BB);
    p1_kernel<<<g1, 256, P1_SMEM>>>(Q, K, mask);

    dim3 g2(LQ / 128, BB);
    p2_kernel<<<g2, 128, P2_SMEM>>>(V, out);
}

// round 2
// speedup vs baseline: 1.2611x; 1.2611x over previous
#include <cuda_runtime.h>
#include <math.h>

#define BB   16
#define LQ   2048
#define LK   2048
#define DD   64
#define DV   64
#define FLOAT_MIN_F (-3.4028234663852886e38f)

// Scratch (device globals are the sanctioned scratch mechanism).
__device__ float g_S[(long long)BB * LQ * LK];   // 268 MB raw scores
__device__ float g_LM[(long long)LQ * LK];       // 16.8 MB: max(log(mask), FMIN)
__device__ float g_m[BB * LK];                   // per-(b,k) column max
__device__ float g_rz[BB * LK];                  // per-(b,k) 1/Z

// Packed fp32x2 FMA: acc.{lo,hi} += a.{lo,hi} * b.{lo,hi}
#define FFMA2(acc, a, b) \
    asm("fma.rn.f32x2 %0, %1, %2, %0;" : "+l"(acc) : "l"(a), "l"(b))
#define UNPACK2(lo, hi, v) \
    asm("mov.b64 {%0, %1}, %2;" : "=f"(lo), "=f"(hi) : "l"(v))

// ---------------------------------------------------------------------------
// Kernel 0: LM = max(log(mask), FMIN), computed once (mask shared over batch).
// ---------------------------------------------------------------------------
__global__ __launch_bounds__(256) void lm_kernel(const float* __restrict__ mask) {
    long long i = (long long)blockIdx.x * 256 + threadIdx.x;   // float4 index
    float4 v = reinterpret_cast<const float4*>(mask)[i];
    v.x = fmaxf(__logf(v.x), FLOAT_MIN_F);
    v.y = fmaxf(__logf(v.y), FLOAT_MIN_F);
    v.z = fmaxf(__logf(v.z), FLOAT_MIN_F);
    v.w = fmaxf(__logf(v.w), FLOAT_MIN_F);
    reinterpret_cast<float4*>(g_LM)[i] = v;
}

// ---------------------------------------------------------------------------
// Phase 1: S = QK^T/8 + LM; write S; per-k-column max and sum(exp).
// Block = (batch, 64 k-columns). 256 threads. Tile 128q x 64k per q-step,
// micro 8x4 (rows ty*8+i, cols tx+16*j). FFMA2 pairs along d.
// Smem rows padded to 66 floats -> conflict-free 8B operand loads.
// ---------------------------------------------------------------------------
__global__ __launch_bounds__(256, 2) void p1_kernel(const float* __restrict__ Q,
                                                    const float* __restrict__ K) {
    extern __shared__ float sm[];
    float* Qs    = sm;             // [128][66]
    float* Ks    = sm + 8448;      // [64][66]
    float* red   = sm + 12672;     // [16][64]
    float* m_run = sm + 13696;     // [64]
    float* z_run = sm + 13760;     // [64]

    const int b   = blockIdx.y;
    const int k0  = blockIdx.x * 64;
    const int tid = threadIdx.x;
    const int ty  = tid >> 4;      // 0..15 : rows ty*8 .. +7
    const int tx  = tid & 15;      // 0..15 : cols tx, tx+16, tx+32, tx+48

    // K tile [64][64] -> Ks rows of 66 (straight copy, coalesced)
    for (int i = tid; i < 64 * 16; i += 256) {
        int r = i >> 4, c4 = i & 15;
        float4 v = *reinterpret_cast<const float4*>(&K[((long long)b * LK + k0 + r) * DD + c4 * 4]);
        float* dst = &Ks[r * 66 + c4 * 4];
        *reinterpret_cast<float2*>(dst)     = make_float2(v.x, v.y);
        *reinterpret_cast<float2*>(dst + 2) = make_float2(v.z, v.w);
    }
    if (tid < 64) { m_run[tid] = -INFINITY; z_run[tid] = 0.0f; }
    __syncthreads();

    for (int q0 = 0; q0 < LQ; q0 += 128) {
        // Q tile [128][64] -> Qs
        for (int i = tid; i < 128 * 16; i += 256) {
            int r = i >> 4, c4 = i & 15;
            float4 v = *reinterpret_cast<const float4*>(&Q[((long long)b * LQ + q0 + r) * DD + c4 * 4]);
            float* dst = &Qs[r * 66 + c4 * 4];
            *reinterpret_cast<float2*>(dst)     = make_float2(v.x, v.y);
            *reinterpret_cast<float2*>(dst + 2) = make_float2(v.z, v.w);
        }
        __syncthreads();

        unsigned long long acc[8][4];
#pragma unroll
        for (int i = 0; i < 8; i++)
#pragma unroll
            for (int j = 0; j < 4; j++) acc[i][j] = 0ull;

#pragma unroll 4
        for (int d2 = 0; d2 < 32; d2++) {          // pairs along d
            unsigned long long A[8], Bv[4];
#pragma unroll
            for (int i = 0; i < 8; i++)
                A[i] = *reinterpret_cast<const unsigned long long*>(&Qs[(ty * 8 + i) * 66 + d2 * 2]);
#pragma unroll
            for (int j = 0; j < 4; j++)
                Bv[j] = *reinterpret_cast<const unsigned long long*>(&Ks[(tx + 16 * j) * 66 + d2 * 2]);
#pragma unroll
            for (int i = 0; i < 8; i++)
#pragma unroll
                for (int j = 0; j < 4; j++) FFMA2(acc[i][j], A[i], Bv[j]);
        }

        // Epilogue: combine pairs, scale, +LM, store S, per-column max
        float sv[8][4];
        float lmax[4];
#pragma unroll
        for (int j = 0; j < 4; j++) lmax[j] = -INFINITY;
#pragma unroll
        for (int i = 0; i < 8; i++) {
            const int q = q0 + ty * 8 + i;
            const float* lmrow = &g_LM[(long long)q * LK + k0];
            float* srow = &g_S[((long long)b * LQ + q) * LK + k0];
#pragma unroll
            for (int j = 0; j < 4; j++) {
                const int k = tx + 16 * j;
                float lo, hi;
                UNPACK2(lo, hi, acc[i][j]);
                float s = (lo + hi) * 0.125f + lmrow[k];
                sv[i][j] = s;
                srow[k] = s;
                lmax[j] = fmaxf(lmax[j], s);
            }
        }
#pragma unroll
        for (int j = 0; j < 4; j++) red[ty * 64 + tx + 16 * j] = lmax[j];
        __syncthreads();

        if (tid < 64) {
            float tm = red[tid];
#pragma unroll
            for (int r = 1; r < 16; r++) tm = fmaxf(tm, red[r * 64 + tid]);
            float m_new = fmaxf(m_run[tid], tm);
            z_run[tid] *= __expf(m_run[tid] - m_new);   // exp(-inf)=0 on first tile
            m_run[tid] = m_new;
        }
        __syncthreads();

        float lsum[4];
#pragma unroll
        for (int j = 0; j < 4; j++) {
            const float mn = m_run[tx + 16 * j];
            float s = 0.0f;
#pragma unroll
            for (int i = 0; i < 8; i++) s += __expf(sv[i][j] - mn);
            lsum[j] = s;
        }
#pragma unroll
        for (int j = 0; j < 4; j++) red[ty * 64 + tx + 16 * j] = lsum[j];
        __syncthreads();
        if (tid < 64) {
            float ts = 0.0f;
#pragma unroll
            for (int r = 0; r < 16; r++) ts += red[r * 64 + tid];
            z_run[tid] += ts;
        }
        __syncthreads();   // also protects Qs/red overwrite next iter
    }

    if (tid < 64) {
        g_m[b * LK + k0 + tid]  = m_run[tid];
        g_rz[b * LK + k0 + tid] = 1.0f / z_run[tid];    // z >= 1 always
    }
}

// ---------------------------------------------------------------------------
// Phase 2: out[b,q,:] = sum_k exp(S - m[k]) * rz[k] * V[k,:]
// Block = (batch, 128 q-rows). 256 threads, micro 8x4, FFMA2 pairs along k.
// Column stats for the whole k-range staged in smem once per block.
// ---------------------------------------------------------------------------
__global__ __launch_bounds__(256, 2) void p2_kernel(const float* __restrict__ V,
                                                    float* __restrict__ out) {
    extern __shared__ float sm[];
    float* Ps  = sm;               // [128][66]  P tile (q-major)
    float* VsT = sm + 8448;        // [64v][66]  V tile transposed (v-major)
    float* ms  = sm + 12672;       // [2048]
    float* rzs = sm + 14720;       // [2048]

    const int b   = blockIdx.y;
    const int q0  = blockIdx.x * 128;
    const int tid = threadIdx.x;
    const int ty  = tid >> 4;      // rows ty*8 .. +7
    const int tx  = tid & 15;      // v-cols tx + 16*j

    for (int i = tid; i < LK; i += 256) {
        ms[i]  = g_m[b * LK + i];
        rzs[i] = g_rz[b * LK + i];
    }

    unsigned long long acc[8][4];
#pragma unroll
    for (int i = 0; i < 8; i++)
#pragma unroll
        for (int j = 0; j < 4; j++) acc[i][j] = 0ull;

    for (int kk0 = 0; kk0 < LK; kk0 += 64) {
        __syncthreads();   // prev FMA done; also orders stats before first use

        // V tile [64k][64v] -> VsT[v][k] (pad 66). Coalesced scalar reads.
        for (int i = tid; i < 64 * 64; i += 256) {
            int k = i >> 6, v = i & 63;
            VsT[v * 66 + k] = V[((long long)b * LK + kk0 + k) * DV + v];
        }

        // P tile: coalesced float4 S reads, exp-normalize, write q-major.
#pragma unroll
        for (int it = 0; it < 8; it++) {
            const int q  = (tid >> 4) + it * 16;
            const int kg = tid & 15;
            float4 s4 = *reinterpret_cast<const float4*>(
                &g_S[((long long)b * LQ + q0 + q) * LK + kk0 + kg * 4]);
            const int kb = kk0 + kg * 4;
            float p0 = __expf(s4.x - ms[kb + 0]) * rzs[kb + 0];
            float p1 = __expf(s4.y - ms[kb + 1]) * rzs[kb + 1];
            float p2 = __expf(s4.z - ms[kb + 2]) * rzs[kb + 2];
            float p3 = __expf(s4.w - ms[kb + 3]) * rzs[kb + 3];
            float* dst = &Ps[q * 66 + kg * 4];
            *reinterpret_cast<float2*>(dst)     = make_float2(p0, p1);
            *reinterpret_cast<float2*>(dst + 2) = make_float2(p2, p3);
        }
        __syncthreads();

        // acc += P @ V, FFMA2 pairs along k
#pragma unroll 4
        for (int k2 = 0; k2 < 32; k2++) {
            unsigned long long A[8], Bv[4];
#pragma unroll
            for (int i = 0; i < 8; i++)
                A[i] = *reinterpret_cast<const unsigned long long*>(&Ps[(ty * 8 + i) * 66 + k2 * 2]);
#pragma unroll
            for (int j = 0; j < 4; j++)
                Bv[j] = *reinterpret_cast<const unsigned long long*>(&VsT[(tx + 16 * j) * 66 + k2 * 2]);
#pragma unroll
            for (int i = 0; i < 8; i++)
#pragma unroll
                for (int j = 0; j < 4; j++) FFMA2(acc[i][j], A[i], Bv[j]);
        }
    }

    // Epilogue: combine even/odd partials, store.
#pragma unroll
    for (int i = 0; i < 8; i++) {
        const int q = q0 + ty * 8 + i;
        float* orow = &out[((long long)b * LQ + q) * DV];
#pragma unroll
        for (int j = 0; j < 4; j++) {
            float lo, hi;
            UNPACK2(lo, hi, acc[i][j]);
            orow[tx + 16 * j] = lo + hi;
        }
    }
}

// ---------------------------------------------------------------------------

extern "C" void kernel_launch(void* const* d_in, const int* in_sizes, int n_in,
                              void* d_out, int out_size) {
    const float* Q    = (const float*)d_in[0];
    const float* K    = (const float*)d_in[1];
    const float* V    = (const float*)d_in[2];
    const float* mask = (const float*)d_in[3];
    float* out        = (float*)d_out;

    const int P1_SMEM = 13824 * (int)sizeof(float);   // 55296 B
    const int P2_SMEM = 16768 * (int)sizeof(float);   // 67072 B

    cudaFuncSetAttribute(p1_kernel, cudaFuncAttributeMaxDynamicSharedMemorySize, P1_SMEM);
    cudaFuncSetAttribute(p2_kernel, cudaFuncAttributeMaxDynamicSharedMemorySize, P2_SMEM);

    lm_kernel<<<(LQ * LK) / 4 / 256, 256>>>(mask);

    dim3 g1(LK / 64, BB);
    p1_kernel<<<g1, 256, P1_SMEM>>>(Q, K);

    dim3 g2(LQ / 128, BB);
    p2_kernel<<<g2, 256, P2_SMEM>>>(V, out);
}

// round 5
// speedup vs baseline: 3.0249x; 2.3986x over previous
#include <cuda_runtime.h>
#include <cuda_bf16.h>
#include <cstdint>
#include <math.h>

#define BB 16
#define LL 2048
#define DDIM 64
#define FLOAT_MIN_F (-3.4028234663852886e38f)
#define PADE 72           // padded row length in bf16 elems
#define PADB 144          // padded row length in bytes (16B multiple)

// ---------------- device scratch ----------------
__device__ __nv_bfloat16 g_Qh[BB * LL * DDIM], g_Ql[BB * LL * DDIM];
__device__ __nv_bfloat16 g_Kh[BB * LL * DDIM], g_Kl[BB * LL * DDIM];
__device__ __nv_bfloat16 g_Vh[BB * LL * DDIM], g_Vl[BB * LL * DDIM];
__device__ float g_LM[(long long)LL * LL];    // max(log(mask),FMIN)  [q][k]
__device__ float g_LMT[(long long)LL * LL];   // transpose            [k][q]
__device__ float g_m[BB * LL], g_rz[BB * LL];

// ---------------- helpers ----------------
__device__ __forceinline__ uint32_t smem_u32(const void* p) {
    return (uint32_t)__cvta_generic_to_shared(p);
}
// pack two floats -> bf16x2 register, first arg in low half
__device__ __forceinline__ uint32_t pack_bf16x2(float lo, float hi) {
    uint32_t r;
    asm("cvt.rn.bf16x2.f32 %0, %1, %2;" : "=r"(r) : "f"(hi), "f"(lo));
    return r;
}
__device__ __forceinline__ float bf_lo(uint32_t h) { return __uint_as_float(h << 16); }
__device__ __forceinline__ float bf_hi(uint32_t h) { return __uint_as_float(h & 0xffff0000u); }

#define LDSM_X4(r, a) asm volatile( \
    "ldmatrix.sync.aligned.m8n8.x4.shared.b16 {%0,%1,%2,%3}, [%4];" \
    : "=r"((r)[0]), "=r"((r)[1]), "=r"((r)[2]), "=r"((r)[3]) : "r"(a))
#define LDSM_X2(r, a) asm volatile( \
    "ldmatrix.sync.aligned.m8n8.x2.shared.b16 {%0,%1}, [%2];" \
    : "=r"((r)[0]), "=r"((r)[1]) : "r"(a))
#define LDSM_X2T(r, a) asm volatile( \
    "ldmatrix.sync.aligned.m8n8.x2.trans.shared.b16 {%0,%1}, [%2];" \
    : "=r"((r)[0]), "=r"((r)[1]) : "r"(a))
#define MMA_BF16(d, a, b) asm volatile( \
    "mma.sync.aligned.m16n8k16.row.col.f32.bf16.bf16.f32 " \
    "{%0,%1,%2,%3}, {%4,%5,%6,%7}, {%8,%9}, {%0,%1,%2,%3};" \
    : "+f"((d)[0]), "+f"((d)[1]), "+f"((d)[2]), "+f"((d)[3]) \
    : "r"((a)[0]), "r"((a)[1]), "r"((a)[2]), "r"((a)[3]), "r"((b)[0]), "r"((b)[1]))

__device__ __forceinline__ void mz_merge(float& m, float& z, float m2, float z2) {
    float mn = fmaxf(m, m2);
    z = z * __expf(m - mn) + z2 * __expf(m2 - mn);
    m = mn;
}

// ---------------- prep kernels ----------------
__global__ __launch_bounds__(256) void prep_lm(const float* __restrict__ mask) {
    __shared__ float t[32][33];
    const int q0 = blockIdx.y * 32, k0 = blockIdx.x * 32;
    for (int r = threadIdx.y; r < 32; r += 8) {
        float v = mask[(long long)(q0 + r) * LL + k0 + threadIdx.x];
        float lm = fmaxf(__logf(v), FLOAT_MIN_F);
        g_LM[(long long)(q0 + r) * LL + k0 + threadIdx.x] = lm;
        t[r][threadIdx.x] = lm;
    }
    __syncthreads();
    for (int r = threadIdx.y; r < 32; r += 8)
        g_LMT[(long long)(k0 + r) * LL + q0 + threadIdx.x] = t[threadIdx.x][r];
}

__global__ __launch_bounds__(256) void prep_split(const float* __restrict__ Q,
                                                  const float* __restrict__ K,
                                                  const float* __restrict__ V) {
    const float* src = blockIdx.y == 0 ? Q : (blockIdx.y == 1 ? K : V);
    uint32_t* h = (uint32_t*)(blockIdx.y == 0 ? g_Qh : (blockIdx.y == 1 ? g_Kh : g_Vh));
    uint32_t* l = (uint32_t*)(blockIdx.y == 0 ? g_Ql : (blockIdx.y == 1 ? g_Kl : g_Vl));
    const int i = blockIdx.x * 256 + threadIdx.x;   // float4 index (524288 total)
    float4 v = ((const float4*)src)[i];
    uint32_t h0 = pack_bf16x2(v.x, v.y);
    uint32_t h1 = pack_bf16x2(v.z, v.w);
    uint32_t l0 = pack_bf16x2(v.x - bf_lo(h0), v.y - bf_hi(h0));
    uint32_t l1 = pack_bf16x2(v.z - bf_lo(h1), v.w - bf_hi(h1));
    h[i * 2] = h0; h[i * 2 + 1] = h1;
    l[i * 2] = l0; l[i * 2 + 1] = l1;
}

// ---------------- phase 1: column stats via S^T = K @ Q^T ----------------
#define P1_KH 0
#define P1_KL 18432
#define P1_QH 36864
#define P1_QL 55296
#define P1_PM 73728
#define P1_PZ 74752
#define P1_RM 75776
#define P1_RZ 76288
#define P1_SMEM 76800

__global__ __launch_bounds__(256, 2) void p1_kernel() {
    extern __shared__ char smc[];
    const int tid = threadIdx.x, lane = tid & 31, wid = tid >> 5;
    const int wm = wid >> 1, wn = wid & 1;      // warp grid 4(M=k) x 2(N=q)
    const int b = blockIdx.y, k0 = blockIdx.x * 128;
    float* pm = (float*)(smc + P1_PM);
    float* pz = (float*)(smc + P1_PZ);
    float* rm = (float*)(smc + P1_RM);
    float* rzs = (float*)(smc + P1_RZ);

    const uint4* kh4 = (const uint4*)g_Kh;
    const uint4* kl4 = (const uint4*)g_Kl;
    for (int i = tid; i < 1024; i += 256) {
        int row = i >> 3, seg = i & 7;
        size_t gi = ((size_t)b * LL + k0 + row) * 8 + seg;
        *(uint4*)(smc + P1_KH + row * PADB + seg * 16) = kh4[gi];
        *(uint4*)(smc + P1_KL + row * PADB + seg * 16) = kl4[gi];
    }
    if (tid < 128) { rm[tid] = -INFINITY; rzs[tid] = 0.0f; }

    const uint32_t sb = smem_u32(smc);
    const int lr8 = lane & 7, lg = lane >> 3;
    const uint32_t a_lane = (uint32_t)(((lg & 1) * 8 + lr8) * PADB + (lg >> 1) * 16);
    const int l16 = lane & 15;
    const uint32_t b_lane = (uint32_t)((l16 & 7) * PADB + (l16 >> 3) * 16);
    const uint32_t aK = sb + P1_KH + (uint32_t)(wm * 32) * PADB + a_lane;
    const uint32_t bQ = sb + P1_QH + (uint32_t)(wn * 64) * PADB + b_lane;

    const uint4* qh4 = (const uint4*)g_Qh;
    const uint4* ql4 = (const uint4*)g_Ql;

    for (int qt = 0; qt < 16; qt++) {
        const int q0 = qt * 128;
        for (int i = tid; i < 1024; i += 256) {
            int row = i >> 3, seg = i & 7;
            size_t gi = ((size_t)b * LL + q0 + row) * 8 + seg;
            *(uint4*)(smc + P1_QH + row * PADB + seg * 16) = qh4[gi];
            *(uint4*)(smc + P1_QL + row * PADB + seg * 16) = ql4[gi];
        }
        __syncthreads();

        float acc[2][8][4];
#pragma unroll
        for (int mt = 0; mt < 2; mt++)
#pragma unroll
            for (int nt = 0; nt < 8; nt++)
#pragma unroll
                for (int r = 0; r < 4; r++) acc[mt][nt][r] = 0.0f;

#pragma unroll
        for (int ks = 0; ks < 4; ks++) {
            uint32_t aH[2][4], aL[2][4];
#pragma unroll
            for (int mt = 0; mt < 2; mt++) {
                LDSM_X4(aH[mt], aK + mt * 16 * PADB + ks * 32);
                LDSM_X4(aL[mt], aK + 18432 + mt * 16 * PADB + ks * 32);
            }
#pragma unroll
            for (int nt = 0; nt < 8; nt++) {
                uint32_t bH[2], bL[2];
                LDSM_X2(bH, bQ + nt * 8 * PADB + ks * 32);
                LDSM_X2(bL, bQ + 18432 + nt * 8 * PADB + ks * 32);
#pragma unroll
                for (int mt = 0; mt < 2; mt++) {
                    MMA_BF16(acc[mt][nt], aH[mt], bH);
                    MMA_BF16(acc[mt][nt], aH[mt], bL);
                    MMA_BF16(acc[mt][nt], aL[mt], bH);
                }
            }
        }

        // epilogue: s = acc/8 + LMT; per-k-row max & sum(exp)
#pragma unroll
        for (int mt = 0; mt < 2; mt++) {
#pragma unroll
            for (int h = 0; h < 2; h++) {
                const int krow = k0 + wm * 32 + mt * 16 + (lane >> 2) + h * 8;
                const float* lmp = g_LMT + (size_t)krow * LL + q0 + wn * 64 + (lane & 3) * 2;
                float mloc = -INFINITY;
#pragma unroll
                for (int nt = 0; nt < 8; nt++) {
                    float2 lm2 = *(const float2*)(lmp + nt * 8);
                    float s0 = acc[mt][nt][2 * h] * 0.125f + lm2.x;
                    float s1 = acc[mt][nt][2 * h + 1] * 0.125f + lm2.y;
                    acc[mt][nt][2 * h] = s0; acc[mt][nt][2 * h + 1] = s1;
                    mloc = fmaxf(mloc, fmaxf(s0, s1));
                }
                float zloc = 0.0f;
#pragma unroll
                for (int nt = 0; nt < 8; nt++)
                    zloc += __expf(acc[mt][nt][2 * h] - mloc) +
                            __expf(acc[mt][nt][2 * h + 1] - mloc);
#pragma unroll
                for (int off = 1; off <= 2; off <<= 1) {
                    float m2 = __shfl_xor_sync(0xffffffffu, mloc, off);
                    float z2 = __shfl_xor_sync(0xffffffffu, zloc, off);
                    mz_merge(mloc, zloc, m2, z2);
                }
                if ((lane & 3) == 0) {
                    int rrow = wm * 32 + mt * 16 + (lane >> 2) + h * 8;
                    pm[wn * 128 + rrow] = mloc;
                    pz[wn * 128 + rrow] = zloc;
                }
            }
        }
        __syncthreads();
        if (tid < 128) {
            mz_merge(rm[tid], rzs[tid], pm[tid], pz[tid]);
            mz_merge(rm[tid], rzs[tid], pm[128 + tid], pz[128 + tid]);
        }
        __syncthreads();
    }
    if (tid < 128) {
        g_m[b * LL + k0 + tid] = rm[tid];
        g_rz[b * LL + k0 + tid] = 1.0f / rzs[tid];
    }
}

// ---------------- phase 2: recompute S, P = exp(S-m)*rz, O += P@V ----------------
#define P2_QH 0
#define P2_QL 18432
#define P2_KH 36864
#define P2_KL 55296
#define P2_VH 73728
#define P2_VL 92160
#define P2_MRZ 110592
#define P2_SMEM 111616
#define P2_OB 36864   // output combine buffer (aliases K region, used after loop)

__global__ __launch_bounds__(256, 1) void p2_kernel(float* __restrict__ out) {
    extern __shared__ char smc[];
    const int tid = threadIdx.x, lane = tid & 31, wid = tid >> 5;
    const int wm = wid >> 1, wn = wid & 1;      // 4(M=q) x 2(N=k-half)
    const int b = blockIdx.y, q0 = blockIdx.x * 128;
    float2* mrzv = (float2*)(smc + P2_MRZ);

    const uint4* qh4 = (const uint4*)g_Qh;
    const uint4* ql4 = (const uint4*)g_Ql;
    for (int i = tid; i < 1024; i += 256) {
        int row = i >> 3, seg = i & 7;
        size_t gi = ((size_t)b * LL + q0 + row) * 8 + seg;
        *(uint4*)(smc + P2_QH + row * PADB + seg * 16) = qh4[gi];
        *(uint4*)(smc + P2_QL + row * PADB + seg * 16) = ql4[gi];
    }

    const uint32_t sb = smem_u32(smc);
    const int lr8 = lane & 7, lg = lane >> 3;
    const uint32_t a_lane = (uint32_t)(((lg & 1) * 8 + lr8) * PADB + (lg >> 1) * 16);
    const int l16 = lane & 15;
    const uint32_t b_lane = (uint32_t)((l16 & 7) * PADB + (l16 >> 3) * 16);
    const uint32_t aQ = sb + P2_QH + (uint32_t)(wm * 32) * PADB + a_lane;
    const uint32_t bK = sb + P2_KH + (uint32_t)(wn * 64) * PADB + b_lane;
    const uint32_t vV = sb + P2_VH + (uint32_t)(wn * 64) * PADB + (uint32_t)(l16 * PADB);

    float oacc[2][8][4];
#pragma unroll
    for (int mt = 0; mt < 2; mt++)
#pragma unroll
        for (int nt = 0; nt < 8; nt++)
#pragma unroll
            for (int r = 0; r < 4; r++) oacc[mt][nt][r] = 0.0f;

    const uint4* kh4 = (const uint4*)g_Kh;
    const uint4* kl4 = (const uint4*)g_Kl;
    const uint4* vh4 = (const uint4*)g_Vh;
    const uint4* vl4 = (const uint4*)g_Vl;

    for (int kc = 0; kc < 16; kc++) {
        const int k0 = kc * 128;
        __syncthreads();   // previous chunk fully consumed
        for (int i = tid; i < 1024; i += 256) {
            int row = i >> 3, seg = i & 7;
            size_t gi = ((size_t)b * LL + k0 + row) * 8 + seg;
            *(uint4*)(smc + P2_KH + row * PADB + seg * 16) = kh4[gi];
            *(uint4*)(smc + P2_KL + row * PADB + seg * 16) = kl4[gi];
            *(uint4*)(smc + P2_VH + row * PADB + seg * 16) = vh4[gi];
            *(uint4*)(smc + P2_VL + row * PADB + seg * 16) = vl4[gi];
        }
        if (tid < 128)
            mrzv[tid] = make_float2(g_m[b * LL + k0 + tid], g_rz[b * LL + k0 + tid]);
        __syncthreads();

        float sacc[2][8][4];
#pragma unroll
        for (int mt = 0; mt < 2; mt++)
#pragma unroll
            for (int nt = 0; nt < 8; nt++)
#pragma unroll
                for (int r = 0; r < 4; r++) sacc[mt][nt][r] = 0.0f;

#pragma unroll
        for (int ks = 0; ks < 4; ks++) {
            uint32_t aH[2][4], aL[2][4];
#pragma unroll
            for (int mt = 0; mt < 2; mt++) {
                LDSM_X4(aH[mt], aQ + mt * 16 * PADB + ks * 32);
                LDSM_X4(aL[mt], aQ + 18432 + mt * 16 * PADB + ks * 32);
            }
#pragma unroll
            for (int nt = 0; nt < 8; nt++) {
                uint32_t bH[2], bL[2];
                LDSM_X2(bH, bK + nt * 8 * PADB + ks * 32);
                LDSM_X2(bL, bK + 18432 + nt * 8 * PADB + ks * 32);
#pragma unroll
                for (int mt = 0; mt < 2; mt++) {
                    MMA_BF16(sacc[mt][nt], aH[mt], bH);
                    MMA_BF16(sacc[mt][nt], aH[mt], bL);
                    MMA_BF16(sacc[mt][nt], aL[mt], bH);
                }
            }
        }

        // fused softmax-apply + PV, one k16 group at a time
#pragma unroll
        for (int kg = 0; kg < 4; kg++) {
            uint32_t pfh[2][4], pfl[2][4];
#pragma unroll
            for (int mt = 0; mt < 2; mt++) {
                const int r0 = q0 + wm * 32 + mt * 16 + (lane >> 2);
#pragma unroll
                for (int ti = 0; ti < 2; ti++) {
                    const int t = 2 * kg + ti;
                    const int kl = wn * 64 + t * 8 + (lane & 3) * 2;
                    float2 mz0 = mrzv[kl], mz1 = mrzv[kl + 1];
                    const float* lmA = g_LM + (size_t)r0 * LL + k0 + kl;
                    float2 lA = *(const float2*)lmA;
                    float2 lB = *(const float2*)(lmA + 8 * LL);
                    float p00 = __expf(sacc[mt][t][0] * 0.125f + lA.x - mz0.x) * mz0.y;
                    float p01 = __expf(sacc[mt][t][1] * 0.125f + lA.y - mz1.x) * mz1.y;
                    float p10 = __expf(sacc[mt][t][2] * 0.125f + lB.x - mz0.x) * mz0.y;
                    float p11 = __expf(sacc[mt][t][3] * 0.125f + lB.y - mz1.x) * mz1.y;
                    uint32_t h0 = pack_bf16x2(p00, p01);
                    uint32_t h1 = pack_bf16x2(p10, p11);
                    pfh[mt][ti * 2] = h0;
                    pfh[mt][ti * 2 + 1] = h1;
                    pfl[mt][ti * 2] = pack_bf16x2(p00 - bf_lo(h0), p01 - bf_hi(h0));
                    pfl[mt][ti * 2 + 1] = pack_bf16x2(p10 - bf_lo(h1), p11 - bf_hi(h1));
                }
            }
#pragma unroll
            for (int nt = 0; nt < 8; nt++) {
                uint32_t vh[2], vl[2];
                LDSM_X2T(vh, vV + kg * 16 * PADB + nt * 16);
                LDSM_X2T(vl, vV + 18432 + kg * 16 * PADB + nt * 16);
#pragma unroll
                for (int mt = 0; mt < 2; mt++) {
                    MMA_BF16(oacc[mt][nt], pfh[mt], vh);
                    MMA_BF16(oacc[mt][nt], pfh[mt], vl);
                    MMA_BF16(oacc[mt][nt], pfl[mt], vh);
                }
            }
        }
    }

    // combine the two k-half warps and store
    __syncthreads();
    float* ob = (float*)(smc + P2_OB);
    if (wn == 1) {
#pragma unroll
        for (int mt = 0; mt < 2; mt++)
#pragma unroll
            for (int nt = 0; nt < 8; nt++)
#pragma unroll
                for (int h = 0; h < 2; h++) {
                    int r = wm * 32 + mt * 16 + (lane >> 2) + h * 8;
                    *(float2*)&ob[r * 66 + nt * 8 + (lane & 3) * 2] =
                        make_float2(oacc[mt][nt][2 * h], oacc[mt][nt][2 * h + 1]);
                }
    }
    __syncthreads();
    if (wn == 0) {
#pragma unroll
        for (int mt = 0; mt < 2; mt++)
#pragma unroll
            for (int nt = 0; nt < 8; nt++)
#pragma unroll
                for (int h = 0; h < 2; h++) {
                    int r = wm * 32 + mt * 16 + (lane >> 2) + h * 8;
                    float2 o2 = *(float2*)&ob[r * 66 + nt * 8 + (lane & 3) * 2];
                    float2 res = make_float2(oacc[mt][nt][2 * h] + o2.x,
                                             oacc[mt][nt][2 * h + 1] + o2.y);
                    *(float2*)&out[((size_t)b * LL + q0 + r) * DDIM + nt * 8 + (lane & 3) * 2] = res;
                }
    }
}

// ---------------------------------------------------------------------------
extern "C" void kernel_launch(void* const* d_in, const int* in_sizes, int n_in,
                              void* d_out, int out_size) {
    const float* Q = (const float*)d_in[0];
    const float* K = (const float*)d_in[1];
    const float* V = (const float*)d_in[2];
    const float* mask = (const float*)d_in[3];
    float* out = (float*)d_out;

    cudaFuncSetAttribute(p1_kernel, cudaFuncAttributeMaxDynamicSharedMemorySize, P1_SMEM);
    cudaFuncSetAttribute(p2_kernel, cudaFuncAttributeMaxDynamicSharedMemorySize, P2_SMEM);

    prep_lm<<<dim3(LL / 32, LL / 32), dim3(32, 8)>>>(mask);
    prep_split<<<dim3((BB * LL * DDIM) / 4 / 256, 3), 256>>>(Q, K, V);

    p1_kernel<<<dim3(LL / 128, BB), 256, P1_SMEM>>>();
    p2_kernel<<<dim3(LL / 128, BB), 256, P2_SMEM>>>(out);
}

// round 6
// speedup vs baseline: 3.3414x; 1.1046x over previous
#include <cuda_runtime.h>
#include <cuda_bf16.h>
#include <cstdint>
#include <math.h>

#define BB 16
#define LL 2048
#define DDIM 64
#define FLOAT_MIN_F (-3.4028234663852886e38f)
#define PADE 72           // padded row length in bf16 elems
#define PADB 144          // padded row length in bytes (16B multiple)

// ---------------- device scratch ----------------
__device__ __nv_bfloat16 g_Qh[BB * LL * DDIM], g_Ql[BB * LL * DDIM];
__device__ __nv_bfloat16 g_Kh[BB * LL * DDIM], g_Kl[BB * LL * DDIM];
__device__ __nv_bfloat16 g_Vh[BB * LL * DDIM], g_Vl[BB * LL * DDIM];
__device__ float g_LM[(long long)LL * LL];    // max(log(mask),FMIN)  [q][k]
__device__ float g_LMT[(long long)LL * LL];   // transpose            [k][q]
__device__ float g_m[BB * LL], g_rz[BB * LL];

// ---------------- helpers ----------------
__device__ __forceinline__ uint32_t smem_u32(const void* p) {
    return (uint32_t)__cvta_generic_to_shared(p);
}
// pack two floats -> bf16x2 register, first arg in low half
__device__ __forceinline__ uint32_t pack_bf16x2(float lo, float hi) {
    uint32_t r;
    asm("cvt.rn.bf16x2.f32 %0, %1, %2;" : "=r"(r) : "f"(hi), "f"(lo));
    return r;
}
__device__ __forceinline__ float bf_lo(uint32_t h) { return __uint_as_float(h << 16); }
__device__ __forceinline__ float bf_hi(uint32_t h) { return __uint_as_float(h & 0xffff0000u); }

#define LDSM_X4(r, a) asm volatile( \
    "ldmatrix.sync.aligned.m8n8.x4.shared.b16 {%0,%1,%2,%3}, [%4];" \
    : "=r"((r)[0]), "=r"((r)[1]), "=r"((r)[2]), "=r"((r)[3]) : "r"(a))
#define LDSM_X2(r, a) asm volatile( \
    "ldmatrix.sync.aligned.m8n8.x2.shared.b16 {%0,%1}, [%2];" \
    : "=r"((r)[0]), "=r"((r)[1]) : "r"(a))
#define LDSM_X2T(r, a) asm volatile( \
    "ldmatrix.sync.aligned.m8n8.x2.trans.shared.b16 {%0,%1}, [%2];" \
    : "=r"((r)[0]), "=r"((r)[1]) : "r"(a))
#define MMA_BF16(d, a, b) asm volatile( \
    "mma.sync.aligned.m16n8k16.row.col.f32.bf16.bf16.f32 " \
    "{%0,%1,%2,%3}, {%4,%5,%6,%7}, {%8,%9}, {%0,%1,%2,%3};" \
    : "+f"((d)[0]), "+f"((d)[1]), "+f"((d)[2]), "+f"((d)[3]) \
    : "r"((a)[0]), "r"((a)[1]), "r"((a)[2]), "r"((a)[3]), "r"((b)[0]), "r"((b)[1]))

#define CP_ASYNC16(dst, src) asm volatile( \
    "cp.async.cg.shared.global [%0], [%1], 16;" :: "r"(dst), "l"(src))
#define CP_COMMIT() asm volatile("cp.async.commit_group;" ::: "memory")
#define CP_WAIT(n)  asm volatile("cp.async.wait_group %0;" :: "n"(n) : "memory")

__device__ __forceinline__ void mz_merge(float& m, float& z, float m2, float z2) {
    float mn = fmaxf(m, m2);
    z = z * __expf(m - mn) + z2 * __expf(m2 - mn);
    m = mn;
}

// ---------------- prep kernels ----------------
__global__ __launch_bounds__(256) void prep_lm(const float* __restrict__ mask) {
    __shared__ float t[32][33];
    const int q0 = blockIdx.y * 32, k0 = blockIdx.x * 32;
    for (int r = threadIdx.y; r < 32; r += 8) {
        float v = mask[(long long)(q0 + r) * LL + k0 + threadIdx.x];
        float lm = fmaxf(__logf(v), FLOAT_MIN_F);
        g_LM[(long long)(q0 + r) * LL + k0 + threadIdx.x] = lm;
        t[r][threadIdx.x] = lm;
    }
    __syncthreads();
    for (int r = threadIdx.y; r < 32; r += 8)
        g_LMT[(long long)(k0 + r) * LL + q0 + threadIdx.x] = t[threadIdx.x][r];
}

__global__ __launch_bounds__(256) void prep_split(const float* __restrict__ Q,
                                                  const float* __restrict__ K,
                                                  const float* __restrict__ V) {
    const float* src = blockIdx.y == 0 ? Q : (blockIdx.y == 1 ? K : V);
    uint32_t* h = (uint32_t*)(blockIdx.y == 0 ? g_Qh : (blockIdx.y == 1 ? g_Kh : g_Vh));
    uint32_t* l = (uint32_t*)(blockIdx.y == 0 ? g_Ql : (blockIdx.y == 1 ? g_Kl : g_Vl));
    const int i = blockIdx.x * 256 + threadIdx.x;   // float4 index (524288 total)
    float4 v = ((const float4*)src)[i];
    uint32_t h0 = pack_bf16x2(v.x, v.y);
    uint32_t h1 = pack_bf16x2(v.z, v.w);
    uint32_t l0 = pack_bf16x2(v.x - bf_lo(h0), v.y - bf_hi(h0));
    uint32_t l1 = pack_bf16x2(v.z - bf_lo(h1), v.w - bf_hi(h1));
    h[i * 2] = h0; h[i * 2 + 1] = h1;
    l[i * 2] = l0; l[i * 2 + 1] = l1;
}

// ---------------- phase 1: column stats via S^T = K @ Q^T ----------------
#define P1_KH 0
#define P1_KL 18432
#define P1_QH 36864
#define P1_QL 55296
#define P1_PM 73728
#define P1_PZ 74752
#define P1_RM 75776
#define P1_RZ 76288
#define P1_SMEM 76800

__global__ __launch_bounds__(256, 2) void p1_kernel() {
    extern __shared__ char smc[];
    const int tid = threadIdx.x, lane = tid & 31, wid = tid >> 5;
    const int wm = wid >> 1, wn = wid & 1;      // warp grid 4(M=k) x 2(N=q)
    const int b = blockIdx.y, k0 = blockIdx.x * 128;
    float* pm = (float*)(smc + P1_PM);
    float* pz = (float*)(smc + P1_PZ);
    float* rm = (float*)(smc + P1_RM);
    float* rzs = (float*)(smc + P1_RZ);

    const uint4* kh4 = (const uint4*)g_Kh;
    const uint4* kl4 = (const uint4*)g_Kl;
    for (int i = tid; i < 1024; i += 256) {
        int row = i >> 3, seg = i & 7;
        size_t gi = ((size_t)b * LL + k0 + row) * 8 + seg;
        *(uint4*)(smc + P1_KH + row * PADB + seg * 16) = kh4[gi];
        *(uint4*)(smc + P1_KL + row * PADB + seg * 16) = kl4[gi];
    }
    if (tid < 128) { rm[tid] = -INFINITY; rzs[tid] = 0.0f; }

    const uint32_t sb = smem_u32(smc);
    const int lr8 = lane & 7, lg = lane >> 3;
    const uint32_t a_lane = (uint32_t)(((lg & 1) * 8 + lr8) * PADB + (lg >> 1) * 16);
    const int l16 = lane & 15;
    const uint32_t b_lane = (uint32_t)((l16 & 7) * PADB + (l16 >> 3) * 16);
    const uint32_t aK = sb + P1_KH + (uint32_t)(wm * 32) * PADB + a_lane;
    const uint32_t bQ = sb + P1_QH + (uint32_t)(wn * 64) * PADB + b_lane;

    const uint4* qh4 = (const uint4*)g_Qh;
    const uint4* ql4 = (const uint4*)g_Ql;

    for (int qt = 0; qt < 16; qt++) {
        const int q0 = qt * 128;
        for (int i = tid; i < 1024; i += 256) {
            int row = i >> 3, seg = i & 7;
            size_t gi = ((size_t)b * LL + q0 + row) * 8 + seg;
            *(uint4*)(smc + P1_QH + row * PADB + seg * 16) = qh4[gi];
            *(uint4*)(smc + P1_QL + row * PADB + seg * 16) = ql4[gi];
        }
        __syncthreads();

        float acc[2][8][4];
#pragma unroll
        for (int mt = 0; mt < 2; mt++)
#pragma unroll
            for (int nt = 0; nt < 8; nt++)
#pragma unroll
                for (int r = 0; r < 4; r++) acc[mt][nt][r] = 0.0f;

#pragma unroll
        for (int ks = 0; ks < 4; ks++) {
            uint32_t aH[2][4], aL[2][4];
#pragma unroll
            for (int mt = 0; mt < 2; mt++) {
                LDSM_X4(aH[mt], aK + mt * 16 * PADB + ks * 32);
                LDSM_X4(aL[mt], aK + 18432 + mt * 16 * PADB + ks * 32);
            }
#pragma unroll
            for (int nt = 0; nt < 8; nt++) {
                uint32_t bH[2], bL[2];
                LDSM_X2(bH, bQ + nt * 8 * PADB + ks * 32);
                LDSM_X2(bL, bQ + 18432 + nt * 8 * PADB + ks * 32);
#pragma unroll
                for (int mt = 0; mt < 2; mt++) {
                    MMA_BF16(acc[mt][nt], aH[mt], bH);
                    MMA_BF16(acc[mt][nt], aH[mt], bL);
                    MMA_BF16(acc[mt][nt], aL[mt], bH);
                }
            }
        }

        // epilogue: s = acc/8 + LMT; per-k-row max & sum(exp)
#pragma unroll
        for (int mt = 0; mt < 2; mt++) {
#pragma unroll
            for (int h = 0; h < 2; h++) {
                const int krow = k0 + wm * 32 + mt * 16 + (lane >> 2) + h * 8;
                const float* lmp = g_LMT + (size_t)krow * LL + q0 + wn * 64 + (lane & 3) * 2;
                float mloc = -INFINITY;
#pragma unroll
                for (int nt = 0; nt < 8; nt++) {
                    float2 lm2 = *(const float2*)(lmp + nt * 8);
                    float s0 = acc[mt][nt][2 * h] * 0.125f + lm2.x;
                    float s1 = acc[mt][nt][2 * h + 1] * 0.125f + lm2.y;
                    acc[mt][nt][2 * h] = s0; acc[mt][nt][2 * h + 1] = s1;
                    mloc = fmaxf(mloc, fmaxf(s0, s1));
                }
                float zloc = 0.0f;
#pragma unroll
                for (int nt = 0; nt < 8; nt++)
                    zloc += __expf(acc[mt][nt][2 * h] - mloc) +
                            __expf(acc[mt][nt][2 * h + 1] - mloc);
#pragma unroll
                for (int off = 1; off <= 2; off <<= 1) {
                    float m2 = __shfl_xor_sync(0xffffffffu, mloc, off);
                    float z2 = __shfl_xor_sync(0xffffffffu, zloc, off);
                    mz_merge(mloc, zloc, m2, z2);
                }
                if ((lane & 3) == 0) {
                    int rrow = wm * 32 + mt * 16 + (lane >> 2) + h * 8;
                    pm[wn * 128 + rrow] = mloc;
                    pz[wn * 128 + rrow] = zloc;
                }
            }
        }
        __syncthreads();
        if (tid < 128) {
            mz_merge(rm[tid], rzs[tid], pm[tid], pz[tid]);
            mz_merge(rm[tid], rzs[tid], pm[128 + tid], pz[128 + tid]);
        }
        __syncthreads();
    }
    if (tid < 128) {
        g_m[b * LL + k0 + tid] = rm[tid];
        g_rz[b * LL + k0 + tid] = 1.0f / rzs[tid];
    }
}

// ---------------- phase 2: recompute S, P = exp(S-m)*rz, O += P@V ----------------
// smem: Q (hi/lo) 36KB; two 72KB K/V buffers; two 1KB m/rz buffers.
#define P2_QH 0
#define P2_QL 18432
#define P2_BUF0 36864
#define P2_BUFSZ 73728            // KH 0, KL 18432, VH 36864, VL 55296
#define P2_MRZ 184320             // per buf: ms (512B) + rz (512B)
#define P2_SMEM 186368
#define P2_OB 36864               // output combine buffer (aliases buf0, post-loop)

__global__ __launch_bounds__(256, 1) void p2_kernel(float* __restrict__ out) {
    extern __shared__ char smc[];
    const int tid = threadIdx.x, lane = tid & 31, wid = tid >> 5;
    const int wm = wid >> 1, wn = wid & 1;      // 4(M=q) x 2(N=k-half)
    const int b = blockIdx.y, q0 = blockIdx.x * 128;
    const uint32_t sb = smem_u32(smc);

    // Q tile (async, lands with first chunk's group)
    for (int i = tid; i < 1024; i += 256) {
        int row = i >> 3, seg = i & 7;
        size_t go = (((size_t)b * LL + q0 + row) * 64) * 2 + seg * 16;
        uint32_t d = sb + row * PADB + seg * 16;
        CP_ASYNC16(d + P2_QH, (const char*)g_Qh + go);
        CP_ASYNC16(d + P2_QL, (const char*)g_Ql + go);
    }

    // chunk prefetch: K/V hi+lo and m/rz into buffer `buf`
    auto prefetch = [&](int kc2, int buf) {
        const uint32_t db = sb + P2_BUF0 + buf * P2_BUFSZ;
        for (int i = tid; i < 1024; i += 256) {
            int row = i >> 3, seg = i & 7;
            size_t go = (((size_t)b * LL + kc2 * 128 + row) * 64) * 2 + seg * 16;
            uint32_t d = db + row * PADB + seg * 16;
            CP_ASYNC16(d + 0,     (const char*)g_Kh + go);
            CP_ASYNC16(d + 18432, (const char*)g_Kl + go);
            CP_ASYNC16(d + 36864, (const char*)g_Vh + go);
            CP_ASYNC16(d + 55296, (const char*)g_Vl + go);
        }
        if (tid < 32) {
            uint32_t d = sb + P2_MRZ + buf * 1024 + tid * 16;
            CP_ASYNC16(d,       (const char*)(g_m  + b * LL + kc2 * 128) + tid * 16);
            CP_ASYNC16(d + 512, (const char*)(g_rz + b * LL + kc2 * 128) + tid * 16);
        }
        CP_COMMIT();
    };
    prefetch(0, 0);

    const int lr8 = lane & 7, lg = lane >> 3;
    const uint32_t a_lane = (uint32_t)(((lg & 1) * 8 + lr8) * PADB + (lg >> 1) * 16);
    const int l16 = lane & 15;
    const uint32_t b_lane = (uint32_t)((l16 & 7) * PADB + (l16 >> 3) * 16);
    const uint32_t aQ = sb + P2_QH + (uint32_t)(wm * 32) * PADB + a_lane;

    float oacc[2][8][4];
#pragma unroll
    for (int mt = 0; mt < 2; mt++)
#pragma unroll
        for (int nt = 0; nt < 8; nt++)
#pragma unroll
            for (int r = 0; r < 4; r++) oacc[mt][nt][r] = 0.0f;

    for (int kc = 0; kc < 16; kc++) {
        const int k0 = kc * 128;
        const int buf = kc & 1;
        if (kc + 1 < 16) { prefetch(kc + 1, buf ^ 1); CP_WAIT(1); }
        else             { CP_WAIT(0); }
        __syncthreads();   // chunk kc visible to all warps

        const uint32_t bufb = sb + P2_BUF0 + buf * P2_BUFSZ;
        const uint32_t bK = bufb + (uint32_t)(wn * 64) * PADB + b_lane;
        const uint32_t vV = bufb + 36864 + (uint32_t)(wn * 64) * PADB + (uint32_t)(l16 * PADB);
        const float* msp  = (const float*)(smc + P2_MRZ + buf * 1024);
        const float* rzsp = msp + 128;

        float sacc[2][8][4];
#pragma unroll
        for (int mt = 0; mt < 2; mt++)
#pragma unroll
            for (int nt = 0; nt < 8; nt++)
#pragma unroll
                for (int r = 0; r < 4; r++) sacc[mt][nt][r] = 0.0f;

#pragma unroll
        for (int ks = 0; ks < 4; ks++) {
            uint32_t aH[2][4], aL[2][4];
#pragma unroll
            for (int mt = 0; mt < 2; mt++) {
                LDSM_X4(aH[mt], aQ + mt * 16 * PADB + ks * 32);
                LDSM_X4(aL[mt], aQ + 18432 + mt * 16 * PADB + ks * 32);
            }
#pragma unroll
            for (int nt = 0; nt < 8; nt++) {
                uint32_t bH[2], bL[2];
                LDSM_X2(bH, bK + nt * 8 * PADB + ks * 32);
                LDSM_X2(bL, bK + 18432 + nt * 8 * PADB + ks * 32);
#pragma unroll
                for (int mt = 0; mt < 2; mt++) {
                    MMA_BF16(sacc[mt][nt], aH[mt], bH);
                    MMA_BF16(sacc[mt][nt], aH[mt], bL);
                    MMA_BF16(sacc[mt][nt], aL[mt], bH);
                }
            }
        }

        // fused softmax-apply + PV, one k16 group at a time
#pragma unroll
        for (int kg = 0; kg < 4; kg++) {
            uint32_t pfh[2][4], pfl[2][4];
#pragma unroll
            for (int mt = 0; mt < 2; mt++) {
                const int r0 = q0 + wm * 32 + mt * 16 + (lane >> 2);
#pragma unroll
                for (int ti = 0; ti < 2; ti++) {
                    const int t = 2 * kg + ti;
                    const int kl = wn * 64 + t * 8 + (lane & 3) * 2;
                    float m0 = msp[kl], m1 = msp[kl + 1];
                    float z0 = rzsp[kl], z1 = rzsp[kl + 1];
                    const float* lmA = g_LM + (size_t)r0 * LL + k0 + kl;
                    float2 lA = *(const float2*)lmA;
                    float2 lB = *(const float2*)(lmA + 8 * LL);
                    float p00 = __expf(sacc[mt][t][0] * 0.125f + lA.x - m0) * z0;
                    float p01 = __expf(sacc[mt][t][1] * 0.125f + lA.y - m1) * z1;
                    float p10 = __expf(sacc[mt][t][2] * 0.125f + lB.x - m0) * z0;
                    float p11 = __expf(sacc[mt][t][3] * 0.125f + lB.y - m1) * z1;
                    uint32_t h0 = pack_bf16x2(p00, p01);
                    uint32_t h1 = pack_bf16x2(p10, p11);
                    pfh[mt][ti * 2] = h0;
                    pfh[mt][ti * 2 + 1] = h1;
                    pfl[mt][ti * 2] = pack_bf16x2(p00 - bf_lo(h0), p01 - bf_hi(h0));
                    pfl[mt][ti * 2 + 1] = pack_bf16x2(p10 - bf_lo(h1), p11 - bf_hi(h1));
                }
            }
#pragma unroll
            for (int nt = 0; nt < 8; nt++) {
                uint32_t vh[2], vl[2];
                LDSM_X2T(vh, vV + kg * 16 * PADB + nt * 16);
                LDSM_X2T(vl, vV + 18432 + kg * 16 * PADB + nt * 16);
#pragma unroll
                for (int mt = 0; mt < 2; mt++) {
                    MMA_BF16(oacc[mt][nt], pfh[mt], vh);
                    MMA_BF16(oacc[mt][nt], pfh[mt], vl);
                    MMA_BF16(oacc[mt][nt], pfl[mt], vh);
                }
            }
        }
        __syncthreads();   // all warps done with buf before next prefetch overwrites it
    }

    // combine the two k-half warps and store
    float* ob = (float*)(smc + P2_OB);
    if (wn == 1) {
#pragma unroll
        for (int mt = 0; mt < 2; mt++)
#pragma unroll
            for (int nt = 0; nt < 8; nt++)
#pragma unroll
                for (int h = 0; h < 2; h++) {
                    int r = wm * 32 + mt * 16 + (lane >> 2) + h * 8;
                    *(float2*)&ob[r * 66 + nt * 8 + (lane & 3) * 2] =
                        make_float2(oacc[mt][nt][2 * h], oacc[mt][nt][2 * h + 1]);
                }
    }
    __syncthreads();
    if (wn == 0) {
#pragma unroll
        for (int mt = 0; mt < 2; mt++)
#pragma unroll
            for (int nt = 0; nt < 8; nt++)
#pragma unroll
                for (int h = 0; h < 2; h++) {
                    int r = wm * 32 + mt * 16 + (lane >> 2) + h * 8;
                    float2 o2 = *(float2*)&ob[r * 66 + nt * 8 + (lane & 3) * 2];
                    float2 res = make_float2(oacc[mt][nt][2 * h] + o2.x,
                                             oacc[mt][nt][2 * h + 1] + o2.y);
                    *(float2*)&out[((size_t)b * LL + q0 + r) * DDIM + nt * 8 + (lane & 3) * 2] = res;
                }
    }
}

// ---------------------------------------------------------------------------
extern "C" void kernel_launch(void* const* d_in, const int* in_sizes, int n_in,
                              void* d_out, int out_size) {
    const float* Q = (const float*)d_in[0];
    const float* K = (const float*)d_in[1];
    const float* V = (const float*)d_in[2];
    const float* mask = (const float*)d_in[3];
    float* out = (float*)d_out;

    cudaFuncSetAttribute(p1_kernel, cudaFuncAttributeMaxDynamicSharedMemorySize, P1_SMEM);
    cudaFuncSetAttribute(p2_kernel, cudaFuncAttributeMaxDynamicSharedMemorySize, P2_SMEM);

    prep_lm<<<dim3(LL / 32, LL / 32), dim3(32, 8)>>>(mask);
    prep_split<<<dim3((BB * LL * DDIM) / 4 / 256, 3), 256>>>(Q, K, V);

    p1_kernel<<<dim3(LL / 128, BB), 256, P1_SMEM>>>();
    p2_kernel<<<dim3(LL / 128, BB), 256, P2_SMEM>>>(out);
}